// round 6
// baseline (speedup 1.0000x reference)
#include <cuda_runtime.h>

#define BH 16
#define NSEQ 2048
#define DD 32
#define MM 64
#define LL 32
#define CC (NSEQ/LL)   // 64 chunks

// Scratch (device globals: no allocation allowed in kernel_launch)
__device__ float g_phi_q[BH*NSEQ*MM];     // 8 MB
__device__ float g_phi_k[BH*NSEQ*MM];     // 8 MB
__device__ float g_skv[BH*CC*MM*DD];      // 8 MB  (chunk KV sums -> exclusive prefix)
__device__ float g_sk [BH*CC*MM];         // 256 KB

// ---------------------------------------------------------------------------
// Kernel 1 (fused): per block = 2 chunks (64 tokens) of one (b,h), 512 threads.
// phi phase: thread = (token, m-group of 8): 4 f4 accumulators (low regs,
// high occupancy); omega reads are 8-addr broadcasts, conflict-free.
// chunk-sum phase: thread = (chunk, m, 8-d group).
// ---------------------------------------------------------------------------
__global__ void __launch_bounds__(512, 2) phi_sum_kernel(
    const float* __restrict__ q, const float* __restrict__ k,
    const float* __restrict__ v, const float* __restrict__ omega)
{
    __shared__ float om_t[DD*MM];    // [d][m] transposed, 8 KB
    __shared__ float xq[64*DD];      // 8 KB (reused for v in phase 2)
    __shared__ float xk[64*DD];      // 8 KB
    __shared__ float pk_s[64*MM];    // [t][m] 16 KB

    int tid = threadIdx.x;
    int blk = blockIdx.x;                    // bh*32 + cc2
    int bh  = blk >> 5;
    int cc2 = blk & 31;                      // superblock of 2 chunks
    int base_tok = bh*NSEQ + cc2*64;

    // omega[m][d] -> om_t[d][m], conflict-free stores
    {
        int m  = tid & 63;
        int d0 = (tid >> 6) * 4;
        #pragma unroll
        for (int jj = 0; jj < 4; jj++) {
            int d = d0 + jj;
            om_t[d*MM + m] = omega[m*DD + d];
        }
    }
    // load 64 tokens of q,k (512 float4 each)
    {
        const float4* q4 = (const float4*)(q + base_tok*DD);
        const float4* k4 = (const float4*)(k + base_tok*DD);
        ((float4*)xq)[tid] = q4[tid];
        ((float4*)xk)[tid] = k4[tid];
    }
    __syncthreads();

    // --- phi phase: t = tid>>3 (token), mg = tid&7 ---
    {
        int t  = tid >> 3;
        int mg = tid & 7;            // m groups {mg*4..+3} and {32+mg*4..+3}
        const float4* om4 = (const float4*)om_t;  // 16 f4 per d-row
        const float4* xq4 = (const float4*)xq;    // 8 f4 per token
        const float4* xk4 = (const float4*)xk;

        float4 aq0={0,0,0,0}, aq1={0,0,0,0};
        float4 ak0={0,0,0,0}, ak1={0,0,0,0};
        float nq=0.f, nk=0.f;

        #pragma unroll
        for (int dc = 0; dc < 8; dc++) {          // 4 d's per iter
            float4 xqv = xq4[t*8 + dc];           // 4-addr broadcast
            float4 xkv = xk4[t*8 + dc];
            float ql[4] = {xqv.x, xqv.y, xqv.z, xqv.w};
            float kl[4] = {xkv.x, xkv.y, xkv.z, xkv.w};
            #pragma unroll
            for (int dd = 0; dd < 4; dd++) {
                int d = dc*4 + dd;
                float4 o0 = om4[d*16 + mg];       // 8-addr 4-way bcast: CF
                float4 o1 = om4[d*16 + 8 + mg];
                float a = ql[dd], c = kl[dd];
                aq0.x += a*o0.x; aq0.y += a*o0.y; aq0.z += a*o0.z; aq0.w += a*o0.w;
                aq1.x += a*o1.x; aq1.y += a*o1.y; aq1.z += a*o1.z; aq1.w += a*o1.w;
                ak0.x += c*o0.x; ak0.y += c*o0.y; ak0.z += c*o0.z; ak0.w += c*o0.w;
                ak1.x += c*o1.x; ak1.y += c*o1.y; ak1.z += c*o1.z; ak1.w += c*o1.w;
                nq += a*a; nk += c*c;
            }
        }
        nq *= 0.5f; nk *= 0.5f;

        #define EXP4(dst, src, n) \
            dst.x = __expf(src.x - n)*0.125f; dst.y = __expf(src.y - n)*0.125f; \
            dst.z = __expf(src.z - n)*0.125f; dst.w = __expf(src.w - n)*0.125f;
        float4 p;
        EXP4(p, aq0, nq); *(float4*)&g_phi_q[(base_tok+t)*MM + mg*4]      = p;
        EXP4(p, aq1, nq); *(float4*)&g_phi_q[(base_tok+t)*MM + 32 + mg*4] = p;
        EXP4(p, ak0, nk);
        *(float4*)&g_phi_k[(base_tok+t)*MM + mg*4] = p;
        *(float4*)&pk_s[t*MM + mg*4] = p;
        EXP4(p, ak1, nk);
        *(float4*)&g_phi_k[(base_tok+t)*MM + 32 + mg*4] = p;
        *(float4*)&pk_s[t*MM + 32 + mg*4] = p;
        #undef EXP4
    }
    __syncthreads();

    // load v into xq buffer (q dead)
    {
        const float4* v4 = (const float4*)(v + base_tok*DD);
        ((float4*)xq)[tid] = v4[tid];
    }
    __syncthreads();

    // --- chunk sums: thread = (ch, m, dg); dg = 8 d's (2 float4) ---
    {
        int ch = tid >> 8;           // chunk 0/1
        int r  = tid & 255;
        int m  = r >> 2;             // 0..63
        int dg = r & 3;              // d group (8 d's)
        const float4* vs4 = (const float4*)xq;
        const float* pk = &pk_s[ch*32*MM];
        float4 a0={0,0,0,0}, a1={0,0,0,0};
        float ks = 0.f;
        #pragma unroll 8
        for (int t = 0; t < LL; t++) {
            float p = pk[t*MM + m];
            float4 v0 = vs4[(ch*32+t)*8 + dg*2 + 0];
            float4 v1 = vs4[(ch*32+t)*8 + dg*2 + 1];
            a0.x += p*v0.x; a0.y += p*v0.y; a0.z += p*v0.z; a0.w += p*v0.w;
            a1.x += p*v1.x; a1.y += p*v1.y; a1.z += p*v1.z; a1.w += p*v1.w;
            ks += p;
        }
        int blkc = bh*CC + cc2*2 + ch;
        float4* skv4 = (float4*)g_skv + (size_t)(blkc*MM + m)*8 + dg*2;
        skv4[0] = a0; skv4[1] = a1;
        if (dg == 0) g_sk[blkc*MM + m] = ks;
    }
}

// ---------------------------------------------------------------------------
// Kernel 2: exclusive prefix scan over chunks (in place), float4 for skv.
// ---------------------------------------------------------------------------
__global__ void scan_kernel()
{
    int idx = blockIdx.x * blockDim.x + threadIdx.x;
    const int NSKV = BH*MM*8;        // float4 series
    if (idx < NSKV) {
        int bh = idx / (MM*8);
        int r  = idx % (MM*8);       // m*8 + d4
        float4* base = (float4*)g_skv + (size_t)bh*CC*MM*8 + r;
        float4 run = {0,0,0,0};
        #pragma unroll 4
        for (int c = 0; c < CC; c++) {
            float4 t = base[(size_t)c*MM*8];
            base[(size_t)c*MM*8] = run;
            run.x += t.x; run.y += t.y; run.z += t.z; run.w += t.w;
        }
    } else if (idx < NSKV + BH*MM) {
        int j  = idx - NSKV;
        int bh = j / MM, m = j % MM;
        float* base = g_sk + bh*CC*MM + m;
        float run = 0.f;
        #pragma unroll 4
        for (int c = 0; c < CC; c++) {
            float t = base[c*MM];
            base[c*MM] = run;
            run += t;
        }
    }
}

// ---------------------------------------------------------------------------
// Kernel 3: per-(bh,chunk) output.
//   Phase A: A = tril(phi_q phi_k^T), den = phi_q.kp + rowsum(A) + 1e-6
//   Phase B: out = (phi_q @ S_prev + A @ v) / den
// ---------------------------------------------------------------------------
__global__ void __launch_bounds__(256) out_kernel(
    const float* __restrict__ v, float* __restrict__ out)
{
    __shared__ float pq_p[LL*68];    // [i][m], row stride 17 f4, 8.5 KB
    __shared__ float buf [MM*DD];    // pk [j][m] in A, then Sp [m][d] in B
    __shared__ float vs  [LL*DD];
    __shared__ float A_p [LL*33];    // [i][j], row stride 33
    __shared__ float kp  [MM];
    __shared__ float den [LL];

    int tid = threadIdx.x;
    int blk = blockIdx.x;
    int base_tok = (blk/CC)*NSEQ + (blk%CC)*LL;

    {
        const float4* gq4 = (const float4*)&g_phi_q[base_tok*MM];
        const float4* gk4 = (const float4*)&g_phi_k[base_tok*MM];
        const float4* gv4 = (const float4*)(v + base_tok*DD);
        float4* pq4w = (float4*)pq_p;
        #pragma unroll
        for (int r = 0; r < 2; r++) {
            int idx = tid + r*256;               // i*16 + m4
            int i = idx >> 4, m4 = idx & 15;
            pq4w[i*17 + m4] = gq4[idx];
            ((float4*)buf)[idx] = gk4[idx];      // pk [j][m]
        }
        ((float4*)vs)[tid] = gv4[tid];
        if (tid < MM) kp[tid] = g_sk[blk*MM + tid];
        if (tid < LL) den[tid] = 1e-6f;
    }
    __syncthreads();

    // --- Phase A: i = lane, warp w owns j = w*4 .. w*4+3 ---
    {
        int i = tid & 31;
        int w = tid >> 5;
        int j0 = w * 4;
        const float4* pq4 = (const float4*)pq_p;
        const float4* pk4 = (const float4*)buf;
        const float4* kp4 = (const float4*)kp;
        float a0=0.f, a1=0.f, a2=0.f, a3=0.f, qk=0.f;
        #pragma unroll
        for (int m4 = 0; m4 < 16; m4++) {
            float4 qv = pq4[i*17 + m4];
            float4 k0 = pk4[(j0+0)*16 + m4];
            float4 k1 = pk4[(j0+1)*16 + m4];
            float4 k2 = pk4[(j0+2)*16 + m4];
            float4 k3 = pk4[(j0+3)*16 + m4];
            float4 kv = kp4[m4];
            a0 += qv.x*k0.x + qv.y*k0.y + qv.z*k0.z + qv.w*k0.w;
            a1 += qv.x*k1.x + qv.y*k1.y + qv.z*k1.z + qv.w*k1.w;
            a2 += qv.x*k2.x + qv.y*k2.y + qv.z*k2.z + qv.w*k2.w;
            a3 += qv.x*k3.x + qv.y*k3.y + qv.z*k3.z + qv.w*k3.w;
            qk += qv.x*kv.x + qv.y*kv.y + qv.z*kv.z + qv.w*kv.w;
        }
        if (j0+0 > i) a0 = 0.f;
        if (j0+1 > i) a1 = 0.f;
        if (j0+2 > i) a2 = 0.f;
        if (j0+3 > i) a3 = 0.f;
        A_p[i*33 + j0+0] = a0;
        A_p[i*33 + j0+1] = a1;
        A_p[i*33 + j0+2] = a2;
        A_p[i*33 + j0+3] = a3;
        float dpart = a0 + a1 + a2 + a3 + (w == 0 ? qk : 0.f);
        atomicAdd(&den[i], dpart);
    }
    __syncthreads();

    // swap buf: pk -> Sp
    {
        const float4* gs4 = (const float4*)&g_skv[(size_t)blk*MM*DD];
        ((float4*)buf)[tid]       = gs4[tid];
        ((float4*)buf)[tid + 256] = gs4[tid + 256];
    }
    __syncthreads();

    // --- Phase B ---
    {
        int i = tid >> 3;
        int g = tid & 7;
        const float4* pq4 = (const float4*)pq_p;
        const float4* Sp4 = (const float4*)buf;
        const float4* vs4 = (const float4*)vs;
        float4 o = {0,0,0,0};
        #pragma unroll
        for (int m4 = 0; m4 < 16; m4++) {
            float4 qv = pq4[i*17 + m4];
            float4 s0 = Sp4[(m4*4+0)*8 + g];
            float4 s1 = Sp4[(m4*4+1)*8 + g];
            float4 s2 = Sp4[(m4*4+2)*8 + g];
            float4 s3 = Sp4[(m4*4+3)*8 + g];
            o.x += qv.x*s0.x + qv.y*s1.x + qv.z*s2.x + qv.w*s3.x;
            o.y += qv.x*s0.y + qv.y*s1.y + qv.z*s2.y + qv.w*s3.y;
            o.z += qv.x*s0.z + qv.y*s1.z + qv.z*s2.z + qv.w*s3.z;
            o.w += qv.x*s0.w + qv.y*s1.w + qv.z*s2.w + qv.w*s3.w;
        }
        #pragma unroll
        for (int j = 0; j < LL; j++) {
            float a = A_p[i*33 + j];
            float4 vv = vs4[j*8 + g];
            o.x += a*vv.x; o.y += a*vv.y; o.z += a*vv.z; o.w += a*vv.w;
        }
        float dinv = 1.0f / den[i];
        float4* o4 = (float4*)&out[(base_tok + i)*DD + g*4];
        *o4 = make_float4(o.x*dinv, o.y*dinv, o.z*dinv, o.w*dinv);
    }
}

// ---------------------------------------------------------------------------
extern "C" void kernel_launch(void* const* d_in, const int* in_sizes, int n_in,
                              void* d_out, int out_size)
{
    const float* q     = (const float*)d_in[0];
    const float* k     = (const float*)d_in[1];
    const float* v     = (const float*)d_in[2];
    const float* omega = (const float*)d_in[3];
    float* out = (float*)d_out;

    phi_sum_kernel<<<BH*CC/2, 512>>>(q, k, v, omega);
    const int scan_threads = BH*MM*8 + BH*MM;
    scan_kernel<<<(scan_threads + 255)/256, 256>>>();
    out_kernel<<<BH*CC, 256>>>(v, out);
}

// round 7
// speedup vs baseline: 1.1411x; 1.1411x over previous
#include <cuda_runtime.h>

#define BH 16
#define NSEQ 2048
#define DD 32
#define MM 64
#define LL 32
#define CC (NSEQ/LL)   // 64 chunks

// Scratch (device globals: no allocation allowed in kernel_launch)
__device__ float g_phi_q[BH*NSEQ*MM];     // 8 MB
__device__ float g_phi_k[BH*NSEQ*MM];     // 8 MB
__device__ float g_skv[BH*CC*MM*DD];      // 8 MB  (chunk KV sums -> exclusive prefix)
__device__ float g_sk [BH*CC*MM];         // 256 KB

// ---------------------------------------------------------------------------
// Kernel 1 (fused, R5 config): per block = 2 chunks (64 tokens), 256 threads.
// phi: thread = (token pair, m-group of 8); omega reads conflict-free,
// reused across 2 tokens x {q,k} -> 36 FMA per 2 LDS.128.
// ---------------------------------------------------------------------------
__global__ void __launch_bounds__(256) phi_sum_kernel(
    const float* __restrict__ q, const float* __restrict__ k,
    const float* __restrict__ v, const float* __restrict__ omega)
{
    __shared__ float om_t[DD*MM];    // [d][m] transposed, 8 KB
    __shared__ float xq[64*DD];      // 8 KB (reused for v in phase 2)
    __shared__ float xk[64*DD];      // 8 KB
    __shared__ float pk_s[64*MM];    // [t][m] 16 KB

    int tid = threadIdx.x;
    int blk = blockIdx.x;                    // bh*32 + cc2
    int bh  = blk >> 5;
    int cc2 = blk & 31;                      // superblock of 2 chunks
    int base_tok = bh*NSEQ + cc2*64;

    // omega[m][d] -> om_t[d][m], conflict-free stores
    {
        int m = tid & 63;
        int d0 = (tid >> 6) * 8;
        #pragma unroll
        for (int jj = 0; jj < 8; jj++) {
            int d = d0 + jj;
            om_t[d*MM + m] = omega[m*DD + d];
        }
    }
    // load 64 tokens of q,k (512 float4 each)
    {
        const float4* q4 = (const float4*)(q + base_tok*DD);
        const float4* k4 = (const float4*)(k + base_tok*DD);
        ((float4*)xq)[tid]       = q4[tid];
        ((float4*)xq)[tid + 256] = q4[tid + 256];
        ((float4*)xk)[tid]       = k4[tid];
        ((float4*)xk)[tid + 256] = k4[tid + 256];
    }
    __syncthreads();

    // --- phi phase ---
    {
        int tp = tid >> 3;           // 0..31 token pair
        int mg = tid & 7;            // m groups {mg*4..+3} and {32+mg*4..+3}
        int t0 = tp*2, t1 = t0+1;
        const float4* om4 = (const float4*)om_t;  // 16 f4 per d-row
        const float4* xq4 = (const float4*)xq;    // 8 f4 per token
        const float4* xk4 = (const float4*)xk;

        float4 aq00={0,0,0,0}, aq01={0,0,0,0};    // [tok0][lo/hi]
        float4 aq10={0,0,0,0}, aq11={0,0,0,0};    // [tok1]
        float4 ak00={0,0,0,0}, ak01={0,0,0,0};
        float4 ak10={0,0,0,0}, ak11={0,0,0,0};
        float nq0=0.f, nq1=0.f, nk0=0.f, nk1=0.f;

        #pragma unroll
        for (int dc = 0; dc < 8; dc++) {          // 4 d's per iter
            float4 xq0 = xq4[t0*8 + dc], xq1 = xq4[t1*8 + dc];
            float4 xk0 = xk4[t0*8 + dc], xk1 = xk4[t1*8 + dc];
            float q0l[4] = {xq0.x, xq0.y, xq0.z, xq0.w};
            float q1l[4] = {xq1.x, xq1.y, xq1.z, xq1.w};
            float k0l[4] = {xk0.x, xk0.y, xk0.z, xk0.w};
            float k1l[4] = {xk1.x, xk1.y, xk1.z, xk1.w};
            #pragma unroll
            for (int dd = 0; dd < 4; dd++) {
                int d = dc*4 + dd;
                float4 o0 = om4[d*16 + mg];       // banks 4mg..4mg+3: CF
                float4 o1 = om4[d*16 + 8 + mg];
                float a = q0l[dd], b = q1l[dd], c = k0l[dd], e = k1l[dd];
                aq00.x += a*o0.x; aq00.y += a*o0.y; aq00.z += a*o0.z; aq00.w += a*o0.w;
                aq01.x += a*o1.x; aq01.y += a*o1.y; aq01.z += a*o1.z; aq01.w += a*o1.w;
                aq10.x += b*o0.x; aq10.y += b*o0.y; aq10.z += b*o0.z; aq10.w += b*o0.w;
                aq11.x += b*o1.x; aq11.y += b*o1.y; aq11.z += b*o1.z; aq11.w += b*o1.w;
                ak00.x += c*o0.x; ak00.y += c*o0.y; ak00.z += c*o0.z; ak00.w += c*o0.w;
                ak01.x += c*o1.x; ak01.y += c*o1.y; ak01.z += c*o1.z; ak01.w += c*o1.w;
                ak10.x += e*o0.x; ak10.y += e*o0.y; ak10.z += e*o0.z; ak10.w += e*o0.w;
                ak11.x += e*o1.x; ak11.y += e*o1.y; ak11.z += e*o1.z; ak11.w += e*o1.w;
                nq0 += a*a; nq1 += b*b; nk0 += c*c; nk1 += e*e;
            }
        }
        nq0 *= 0.5f; nq1 *= 0.5f; nk0 *= 0.5f; nk1 *= 0.5f;

        #define EXP4(dst, src, n) \
            dst.x = __expf(src.x - n)*0.125f; dst.y = __expf(src.y - n)*0.125f; \
            dst.z = __expf(src.z - n)*0.125f; dst.w = __expf(src.w - n)*0.125f;
        float4 p;
        EXP4(p, aq00, nq0); *(float4*)&g_phi_q[(base_tok+t0)*MM + mg*4]      = p;
        EXP4(p, aq01, nq0); *(float4*)&g_phi_q[(base_tok+t0)*MM + 32 + mg*4] = p;
        EXP4(p, aq10, nq1); *(float4*)&g_phi_q[(base_tok+t1)*MM + mg*4]      = p;
        EXP4(p, aq11, nq1); *(float4*)&g_phi_q[(base_tok+t1)*MM + 32 + mg*4] = p;
        EXP4(p, ak00, nk0);
        *(float4*)&g_phi_k[(base_tok+t0)*MM + mg*4] = p;
        *(float4*)&pk_s[t0*MM + mg*4] = p;
        EXP4(p, ak01, nk0);
        *(float4*)&g_phi_k[(base_tok+t0)*MM + 32 + mg*4] = p;
        *(float4*)&pk_s[t0*MM + 32 + mg*4] = p;
        EXP4(p, ak10, nk1);
        *(float4*)&g_phi_k[(base_tok+t1)*MM + mg*4] = p;
        *(float4*)&pk_s[t1*MM + mg*4] = p;
        EXP4(p, ak11, nk1);
        *(float4*)&g_phi_k[(base_tok+t1)*MM + 32 + mg*4] = p;
        *(float4*)&pk_s[t1*MM + 32 + mg*4] = p;
        #undef EXP4
    }
    __syncthreads();

    // load v into xq buffer (q dead)
    {
        const float4* v4 = (const float4*)(v + base_tok*DD);
        ((float4*)xq)[tid]       = v4[tid];
        ((float4*)xq)[tid + 256] = v4[tid + 256];
    }
    __syncthreads();

    // --- chunk sums: 128 threads per chunk; thread = (m, d-half) ---
    {
        int ch = tid >> 7;           // chunk 0/1
        int r  = tid & 127;
        int m  = r >> 1;             // 0..63
        int dh = r & 1;              // d half (16 d's = 4 float4)
        const float4* vs4 = (const float4*)xq;
        const float* pk = &pk_s[ch*32*MM];
        float4 a0={0,0,0,0}, a1={0,0,0,0}, a2={0,0,0,0}, a3={0,0,0,0};
        float ks = 0.f;
        #pragma unroll 8
        for (int t = 0; t < LL; t++) {
            float p = pk[t*MM + m];
            float4 v0 = vs4[(ch*32+t)*8 + dh*4 + 0];
            float4 v1 = vs4[(ch*32+t)*8 + dh*4 + 1];
            float4 v2 = vs4[(ch*32+t)*8 + dh*4 + 2];
            float4 v3 = vs4[(ch*32+t)*8 + dh*4 + 3];
            a0.x += p*v0.x; a0.y += p*v0.y; a0.z += p*v0.z; a0.w += p*v0.w;
            a1.x += p*v1.x; a1.y += p*v1.y; a1.z += p*v1.z; a1.w += p*v1.w;
            a2.x += p*v2.x; a2.y += p*v2.y; a2.z += p*v2.z; a2.w += p*v2.w;
            a3.x += p*v3.x; a3.y += p*v3.y; a3.z += p*v3.z; a3.w += p*v3.w;
            ks += p;
        }
        int blkc = bh*CC + cc2*2 + ch;
        float4* skv4 = (float4*)g_skv + (size_t)(blkc*MM + m)*8 + dh*4;
        skv4[0] = a0; skv4[1] = a1; skv4[2] = a2; skv4[3] = a3;
        if (dh == 0) g_sk[blkc*MM + m] = ks;
    }
}

// ---------------------------------------------------------------------------
// Kernel 2: exclusive prefix scan over chunks (in place), float4 for skv.
// ---------------------------------------------------------------------------
__global__ void scan_kernel()
{
    int idx = blockIdx.x * blockDim.x + threadIdx.x;
    const int NSKV = BH*MM*8;        // float4 series
    if (idx < NSKV) {
        int bh = idx / (MM*8);
        int r  = idx % (MM*8);       // m*8 + d4
        float4* base = (float4*)g_skv + (size_t)bh*CC*MM*8 + r;
        float4 run = {0,0,0,0};
        #pragma unroll 4
        for (int c = 0; c < CC; c++) {
            float4 t = base[(size_t)c*MM*8];
            base[(size_t)c*MM*8] = run;
            run.x += t.x; run.y += t.y; run.z += t.z; run.w += t.w;
        }
    } else if (idx < NSKV + BH*MM) {
        int j  = idx - NSKV;
        int bh = j / MM, m = j % MM;
        float* base = g_sk + bh*CC*MM + m;
        float run = 0.f;
        #pragma unroll 4
        for (int c = 0; c < CC; c++) {
            float t = base[c*MM];
            base[c*MM] = run;
            run += t;
        }
    }
}

// ---------------------------------------------------------------------------
// Kernel 3: per-(bh,chunk) output.
//   Phase A: A = tril(phi_q phi_k^T), den = phi_q.kp + rowsum(A) + 1e-6
//   Phase B: out = (phi_q @ S_prev + A @ v) / den
// Sp LDG issued at kernel start into registers (latency hidden under Phase A),
// stored to the buf overlay after pk is dead.
// ---------------------------------------------------------------------------
__global__ void __launch_bounds__(256) out_kernel(
    const float* __restrict__ v, float* __restrict__ out)
{
    __shared__ float pq_p[LL*68];    // [i][m], row stride 17 f4, 8.5 KB
    __shared__ float buf [MM*DD];    // pk [j][m] in A, then Sp [m][d] in B
    __shared__ float vs  [LL*DD];
    __shared__ float A_p [LL*33];    // [i][j], row stride 33
    __shared__ float kp  [MM];
    __shared__ float den [LL];

    int tid = threadIdx.x;
    int blk = blockIdx.x;
    int base_tok = (blk/CC)*NSEQ + (blk%CC)*LL;

    // Early Sp loads -> registers (consumed after Phase A)
    const float4* gs4 = (const float4*)&g_skv[(size_t)blk*MM*DD];
    float4 sp_r0 = gs4[tid];
    float4 sp_r1 = gs4[tid + 256];

    {
        const float4* gq4 = (const float4*)&g_phi_q[base_tok*MM];
        const float4* gk4 = (const float4*)&g_phi_k[base_tok*MM];
        const float4* gv4 = (const float4*)(v + base_tok*DD);
        float4* pq4w = (float4*)pq_p;
        #pragma unroll
        for (int r = 0; r < 2; r++) {
            int idx = tid + r*256;               // i*16 + m4
            int i = idx >> 4, m4 = idx & 15;
            pq4w[i*17 + m4] = gq4[idx];
            ((float4*)buf)[idx] = gk4[idx];      // pk [j][m]
        }
        ((float4*)vs)[tid] = gv4[tid];
        if (tid < MM) kp[tid] = g_sk[blk*MM + tid];
        if (tid < LL) den[tid] = 1e-6f;
    }
    __syncthreads();

    // --- Phase A: i = lane, warp w owns j = w*4 .. w*4+3 ---
    {
        int i = tid & 31;
        int w = tid >> 5;
        int j0 = w * 4;
        const float4* pq4 = (const float4*)pq_p;
        const float4* pk4 = (const float4*)buf;
        const float4* kp4 = (const float4*)kp;
        float a0=0.f, a1=0.f, a2=0.f, a3=0.f, qk=0.f;
        #pragma unroll
        for (int m4 = 0; m4 < 16; m4++) {
            float4 qv = pq4[i*17 + m4];
            float4 k0 = pk4[(j0+0)*16 + m4];
            float4 k1 = pk4[(j0+1)*16 + m4];
            float4 k2 = pk4[(j0+2)*16 + m4];
            float4 k3 = pk4[(j0+3)*16 + m4];
            float4 kv = kp4[m4];
            a0 += qv.x*k0.x + qv.y*k0.y + qv.z*k0.z + qv.w*k0.w;
            a1 += qv.x*k1.x + qv.y*k1.y + qv.z*k1.z + qv.w*k1.w;
            a2 += qv.x*k2.x + qv.y*k2.y + qv.z*k2.z + qv.w*k2.w;
            a3 += qv.x*k3.x + qv.y*k3.y + qv.z*k3.z + qv.w*k3.w;
            qk += qv.x*kv.x + qv.y*kv.y + qv.z*kv.z + qv.w*kv.w;
        }
        if (j0+0 > i) a0 = 0.f;
        if (j0+1 > i) a1 = 0.f;
        if (j0+2 > i) a2 = 0.f;
        if (j0+3 > i) a3 = 0.f;
        A_p[i*33 + j0+0] = a0;
        A_p[i*33 + j0+1] = a1;
        A_p[i*33 + j0+2] = a2;
        A_p[i*33 + j0+3] = a3;
        float dpart = a0 + a1 + a2 + a3 + (w == 0 ? qk : 0.f);
        atomicAdd(&den[i], dpart);
    }
    __syncthreads();

    // pk dead: store prefetched Sp registers into buf
    ((float4*)buf)[tid]       = sp_r0;
    ((float4*)buf)[tid + 256] = sp_r1;
    __syncthreads();

    // --- Phase B ---
    {
        int i = tid >> 3;
        int g = tid & 7;
        const float4* pq4 = (const float4*)pq_p;
        const float4* Sp4 = (const float4*)buf;
        const float4* vs4 = (const float4*)vs;
        float4 o = {0,0,0,0};
        #pragma unroll
        for (int m4 = 0; m4 < 16; m4++) {
            float4 qv = pq4[i*17 + m4];
            float4 s0 = Sp4[(m4*4+0)*8 + g];
            float4 s1 = Sp4[(m4*4+1)*8 + g];
            float4 s2 = Sp4[(m4*4+2)*8 + g];
            float4 s3 = Sp4[(m4*4+3)*8 + g];
            o.x += qv.x*s0.x + qv.y*s1.x + qv.z*s2.x + qv.w*s3.x;
            o.y += qv.x*s0.y + qv.y*s1.y + qv.z*s2.y + qv.w*s3.y;
            o.z += qv.x*s0.z + qv.y*s1.z + qv.z*s2.z + qv.w*s3.z;
            o.w += qv.x*s0.w + qv.y*s1.w + qv.z*s2.w + qv.w*s3.w;
        }
        #pragma unroll
        for (int j = 0; j < LL; j++) {
            float a = A_p[i*33 + j];
            float4 vv = vs4[j*8 + g];
            o.x += a*vv.x; o.y += a*vv.y; o.z += a*vv.z; o.w += a*vv.w;
        }
        float dinv = 1.0f / den[i];
        float4* o4 = (float4*)&out[(base_tok + i)*DD + g*4];
        *o4 = make_float4(o.x*dinv, o.y*dinv, o.z*dinv, o.w*dinv);
    }
}

// ---------------------------------------------------------------------------
extern "C" void kernel_launch(void* const* d_in, const int* in_sizes, int n_in,
                              void* d_out, int out_size)
{
    const float* q     = (const float*)d_in[0];
    const float* k     = (const float*)d_in[1];
    const float* v     = (const float*)d_in[2];
    const float* omega = (const float*)d_in[3];
    float* out = (float*)d_out;

    phi_sum_kernel<<<BH*CC/2, 256>>>(q, k, v, omega);
    const int scan_threads = BH*MM*8 + BH*MM;
    scan_kernel<<<(scan_threads + 255)/256, 256>>>();
    out_kernel<<<BH*CC, 256>>>(v, out);
}